// round 13
// baseline (speedup 1.0000x reference)
#include <cuda_runtime.h>

#define SQ   1024
#define BS   64
#define HD   512
#define ED   256
#define VB   32000
#define G3   1536
#define EOSV 2
#define NEOS 32

#define NBG  8            // batch groups (8 rows each) = clusters
#define CLU  16           // CTAs per cluster; rank owns 32 j-dims
#define NCTA (NBG*CLU)    // 128 CTAs = 8 clusters of 16 (1 per GPC)

#define PSTR 26           // psum row stride (floats): 24 used, bank-clean
#define SM_HBUF (8*HD)                     // one h buffer (floats)
#define SM_H    (2*SM_HBUF)                // double-buffered: 32KB
#define SM_PSUM (256*PSTR)                 // 26624B
#define GRU_SMEM ((SM_H + SM_PSUM) * 4)    // 59392B

typedef unsigned long long u64;

// ------------------- device scratch (static only; no allocs) ----------------
__device__ float g_Gtab[(size_t)VB * G3];   // ~197MB input-projection table
__device__ int   g_dest[SQ * BS];           // EOS compaction slot or -1

// ------------------- packed f32x2 helpers ----------------------------------
__device__ __forceinline__ u64 ffma2(u64 a, u64 b, u64 c) {
    u64 d;
    asm("fma.rn.f32x2 %0, %1, %2, %3;" : "=l"(d) : "l"(a), "l"(b), "l"(c));
    return d;
}
__device__ __forceinline__ float2 unpack2(u64 v) {
    float2 f;
    asm("mov.b64 {%0, %1}, %2;" : "=f"(f.x), "=f"(f.y) : "l"(v));
    return f;
}
__device__ __forceinline__ float hsum2(u64 v) {
    float2 f = unpack2(v);
    return f.x + f.y;
}
__device__ __forceinline__ u64 bcast2(float x) {
    u64 d;
    asm("mov.b64 %0, {%1, %1};" : "=l"(d) : "f"(x));
    return d;
}
__device__ __forceinline__ unsigned smem_u32(const void* p) {
    unsigned a;
    asm("{ .reg .u64 t; cvta.to.shared.u64 t, %1; cvt.u32.u64 %0, t; }"
        : "=r"(a) : "l"(p));
    return a;
}
__device__ __forceinline__ unsigned ctarank() {
    unsigned r;
    asm("mov.u32 %0, %%cluster_ctarank;" : "=r"(r));
    return r;
}
__device__ __forceinline__ void dsmem_store(unsigned laddr, unsigned rank, float v) {
    unsigned ra;
    asm("mapa.shared::cluster.u32 %0, %1, %2;" : "=r"(ra) : "r"(laddr), "r"(rank));
    asm volatile("st.shared::cluster.f32 [%0], %1;" :: "r"(ra), "f"(v) : "memory");
}

// ------------------- Gtab GEMM (+fused prep): G = w_ih * emb^T + b_ih ------
__global__ void __launch_bounds__(256) gtab_kernel(
    const float* __restrict__ emb,
    const float* __restrict__ w_ih,
    const float* __restrict__ b_ih,
    const int*   __restrict__ tokens)
{
    // ---- fused prep: EOS destination scan (first 64 flat CTAs, warp 0) ----
    int fid = blockIdx.y * 12 + blockIdx.x;
    if (fid < BS && threadIdx.x < 32) {
        int b = fid, t = threadIdx.x;
        int s0 = t * 32;
        int cnt = 0;
        #pragma unroll
        for (int i = 0; i < 32; i++) cnt += (tokens[b * SQ + s0 + i] == EOSV);
        int pre = cnt;
        #pragma unroll
        for (int m = 1; m < 32; m <<= 1) {
            int v = __shfl_up_sync(0xffffffffu, pre, m);
            if (t >= m) pre += v;
        }
        pre -= cnt;
        int k = pre;
        #pragma unroll
        for (int i = 0; i < 32; i++) {
            int s = s0 + i;
            bool e = (tokens[b * SQ + s] == EOSV);
            g_dest[s * BS + b] = (e && k < NEOS) ? k : -1;
            k += e;
        }
    }

    // ---- GEMM: 128x128 tile, 16-k steps, 8x8 microtile, f32x2 ----
    __shared__ float A_sT[16 * 132];
    __shared__ float B_sT[16 * 132];

    int tid = threadIdx.x;
    int tx = tid & 15, ty = tid >> 4;
    int g0 = blockIdx.x * 128;
    int t0 = blockIdx.y * 128;

    u64 acc[8][4];
    #pragma unroll
    for (int i = 0; i < 8; i++)
        #pragma unroll
        for (int j = 0; j < 4; j++) acc[i][j] = 0ull;

    for (int k0 = 0; k0 < ED; k0 += 16) {
        __syncthreads();
        #pragma unroll
        for (int i = 0; i < 2; i++) {
            int ff  = tid + i * 256;
            int row = ff >> 2;
            int c4  = (ff & 3) * 4;
            float4 va = *(const float4*)&emb[(size_t)(t0 + row) * ED + k0 + c4];
            A_sT[(c4 + 0) * 132 + row] = va.x;
            A_sT[(c4 + 1) * 132 + row] = va.y;
            A_sT[(c4 + 2) * 132 + row] = va.z;
            A_sT[(c4 + 3) * 132 + row] = va.w;
            float4 vb = *(const float4*)&w_ih[(size_t)(g0 + row) * ED + k0 + c4];
            B_sT[(c4 + 0) * 132 + row] = vb.x;
            B_sT[(c4 + 1) * 132 + row] = vb.y;
            B_sT[(c4 + 2) * 132 + row] = vb.z;
            B_sT[(c4 + 3) * 132 + row] = vb.w;
        }
        __syncthreads();
        #pragma unroll
        for (int k = 0; k < 16; k++) {
            float4 a0 = *(const float4*)&A_sT[k * 132 + ty * 4];
            float4 a1 = *(const float4*)&A_sT[k * 132 + 64 + ty * 4];
            u64 b0x = *(const u64*)&B_sT[k * 132 + tx * 4];
            u64 b0y = *(const u64*)&B_sT[k * 132 + tx * 4 + 2];
            u64 b1x = *(const u64*)&B_sT[k * 132 + 64 + tx * 4];
            u64 b1y = *(const u64*)&B_sT[k * 132 + 64 + tx * 4 + 2];
            float af[8] = {a0.x, a0.y, a0.z, a0.w, a1.x, a1.y, a1.z, a1.w};
            #pragma unroll
            for (int i = 0; i < 8; i++) {
                u64 ap = bcast2(af[i]);
                acc[i][0] = ffma2(ap, b0x, acc[i][0]);
                acc[i][1] = ffma2(ap, b0y, acc[i][1]);
                acc[i][2] = ffma2(ap, b1x, acc[i][2]);
                acc[i][3] = ffma2(ap, b1y, acc[i][3]);
            }
        }
    }

    float4 bia0 = *(const float4*)&b_ih[g0 + tx * 4];
    float4 bia1 = *(const float4*)&b_ih[g0 + 64 + tx * 4];
    #pragma unroll
    for (int i = 0; i < 8; i++) {
        int trow = t0 + (i >> 2) * 64 + ty * 4 + (i & 3);
        float2 c0 = unpack2(acc[i][0]);
        float2 c1 = unpack2(acc[i][1]);
        float2 c2 = unpack2(acc[i][2]);
        float2 c3 = unpack2(acc[i][3]);
        float4 o0 = make_float4(c0.x + bia0.x, c0.y + bia0.y, c1.x + bia0.z, c1.y + bia0.w);
        float4 o1 = make_float4(c2.x + bia1.x, c2.y + bia1.y, c3.x + bia1.z, c3.y + bia1.w);
        *(float4*)&g_Gtab[(size_t)trow * G3 + g0 + tx * 4]      = o0;
        *(float4*)&g_Gtab[(size_t)trow * G3 + g0 + 64 + tx * 4] = o1;
    }
}

// ------------------- persistent GRU recurrence (cluster DSMEM) --------------
// 8 clusters of 16 CTAs; cluster = batch group (8 batches), rank = 32 j-dims.
// No grid barrier, no global h: each step's hnew is pushed into all 16 peers'
// double-buffered SMEM via mapa+st.shared::cluster; barrier.cluster
// (release/acquire, ~380cyc HW) makes the stores visible cluster-wide.
// Thread (ks=tid>>4 in 0..15: 32-elem K slice; jl=tid&15); owns 2 j's
// (jl, 16+jl). Warp = 16 broadcast lanes x 2 ks (rotated -> disjoint banks).
__global__ void __launch_bounds__(256, 1) gru_kernel(
    const int*   __restrict__ tokens,
    const float* __restrict__ w_hh,
    const float* __restrict__ b_hh,
    float*       __restrict__ out)
{
    extern __shared__ float sm[];
    float* hbuf = sm;                  // [2][8][512]
    float* psum = sm + SM_H;           // [256][PSTR]

    int tid = threadIdx.x;
    int bg = blockIdx.x >> 4;
    unsigned rank = ctarank();         // 0..15
    int ks = tid >> 4;                 // 0..15 (32-elem k slice)
    int jl = tid & 15;
    int jA = rank * 32 + jl;           // first owned j
    int jB = jA + 16;                  // second owned j

    // one-time W_hh register slice: 2 j x 3 gates x 32 K, rotated f4 order
    u64 wra[16], wza[16], wna[16], wrb[16], wzb[16], wnb[16];
    #pragma unroll
    for (int i4 = 0; i4 < 8; i4++) {
        int col = ks * 32 + ((i4 + 4 * ks) & 7) * 4;
        const float* ra0 = &w_hh[(size_t)(0 * HD + jA) * HD + col];
        const float* ra1 = &w_hh[(size_t)(1 * HD + jA) * HD + col];
        const float* ra2 = &w_hh[(size_t)(2 * HD + jA) * HD + col];
        const float* rb0 = &w_hh[(size_t)(0 * HD + jB) * HD + col];
        const float* rb1 = &w_hh[(size_t)(1 * HD + jB) * HD + col];
        const float* rb2 = &w_hh[(size_t)(2 * HD + jB) * HD + col];
        wra[2*i4] = *(const u64*)ra0;  wra[2*i4+1] = *(const u64*)(ra0 + 2);
        wza[2*i4] = *(const u64*)ra1;  wza[2*i4+1] = *(const u64*)(ra1 + 2);
        wna[2*i4] = *(const u64*)ra2;  wna[2*i4+1] = *(const u64*)(ra2 + 2);
        wrb[2*i4] = *(const u64*)rb0;  wrb[2*i4+1] = *(const u64*)(rb0 + 2);
        wzb[2*i4] = *(const u64*)rb1;  wzb[2*i4+1] = *(const u64*)(rb1 + 2);
        wnb[2*i4] = *(const u64*)rb2;  wnb[2*i4+1] = *(const u64*)(rb2 + 2);
    }

    // phase-2 / prefetch role: one (batch, j) per thread
    int b2  = tid >> 5;                // 0..7
    int jj2 = tid & 31;                // 0..31
    int bG2 = bg * 8 + b2;
    int jG2 = rank * 32 + jj2;
    float bhr = b_hh[jG2], bhz = b_hh[HD + jG2], bhn = b_hh[2 * HD + jG2];

    int tok0 = __ldg(&tokens[bG2 * SQ]);
    const float* gp0 = &g_Gtab[(size_t)tok0 * G3 + jG2];
    float pr = __ldcs(gp0), pz = __ldcs(gp0 + HD), pn = __ldcs(gp0 + 2 * HD);
    int pd = __ldg(&g_dest[bG2]);

    bool store_lane = ((ks & 1) == 0);
    int  slot = ks >> 1;               // 0..7

    unsigned smbase = smem_u32(sm);

    // zero both h buffers, then cluster sync so no peer's step-0 store
    // races our zeroing
    for (int i = tid; i < SM_H; i += 256) sm[i] = 0.f;
    __syncthreads();
    asm volatile("barrier.cluster.arrive.aligned;" ::: "memory");
    asm volatile("barrier.cluster.wait.aligned;"   ::: "memory");

    for (int s = 0; s < SQ; s++) {
        int p = s & 1;
        const float* hp = hbuf + p * SM_HBUF;

        // ---- phase 1: per batch, 6 chains (2 j x 3 gates) over own K slice
        #pragma unroll 2
        for (int b = 0; b < 8; b++) {
            const float* hb = hp + b * HD;
            u64 aar = 0, aaz = 0, aan = 0, abr = 0, abz = 0, abn = 0;
            #pragma unroll
            for (int i4 = 0; i4 < 8; i4++) {
                int col = ks * 32 + ((i4 + 4 * ks) & 7) * 4;
                ulonglong2 hv = *(const ulonglong2*)&hb[col];
                aar = ffma2(wra[2*i4], hv.x, aar);
                abr = ffma2(wrb[2*i4], hv.x, abr);
                aaz = ffma2(wza[2*i4], hv.x, aaz);
                abz = ffma2(wzb[2*i4], hv.x, abz);
                aan = ffma2(wna[2*i4], hv.x, aan);
                abn = ffma2(wnb[2*i4], hv.x, abn);
                aar = ffma2(wra[2*i4+1], hv.y, aar);
                abr = ffma2(wrb[2*i4+1], hv.y, abr);
                aaz = ffma2(wza[2*i4+1], hv.y, aaz);
                abz = ffma2(wzb[2*i4+1], hv.y, abz);
                aan = ffma2(wna[2*i4+1], hv.y, aan);
                abn = ffma2(wnb[2*i4+1], hv.y, abn);
            }
            float var = hsum2(aar), vaz = hsum2(aaz), van = hsum2(aan);
            float vbr = hsum2(abr), vbz = hsum2(abz), vbn = hsum2(abn);
            // combine ks-pair (same jl, lane^16)
            var += __shfl_xor_sync(0xffffffffu, var, 16);
            vaz += __shfl_xor_sync(0xffffffffu, vaz, 16);
            van += __shfl_xor_sync(0xffffffffu, van, 16);
            vbr += __shfl_xor_sync(0xffffffffu, vbr, 16);
            vbz += __shfl_xor_sync(0xffffffffu, vbz, 16);
            vbn += __shfl_xor_sync(0xffffffffu, vbn, 16);
            if (store_lane) {
                float* pA = &psum[(b * 32 + jl) * PSTR];
                float* pB = &psum[(b * 32 + 16 + jl) * PSTR];
                pA[slot] = var;  pA[8 + slot] = vaz;  pA[16 + slot] = van;
                pB[slot] = vbr;  pB[8 + slot] = vbz;  pB[16 + slot] = vbn;
            }
        }

        // ---- prefetch gi(s+1)/dest(s+1) ----
        float nr = 0.f, nz = 0.f, nn2 = 0.f;
        int nd = -1;
        if (s + 1 < SQ) {
            int tk = __ldg(&tokens[bG2 * SQ + s + 1]);
            const float* gq = &g_Gtab[(size_t)tk * G3 + jG2];
            nr  = __ldcs(gq);
            nz  = __ldcs(gq + HD);
            nn2 = __ldcs(gq + 2 * HD);
            nd  = __ldg(&g_dest[(s + 1) * BS + bG2]);
        }
        __syncthreads();

        // ---- phase 2: reduce 8 slots/gate, gates, DSMEM broadcast ----
        {
            const float* pp = &psum[tid * PSTR];
            float2 q0 = *(const float2*)&pp[0],  q1 = *(const float2*)&pp[2];
            float2 q2 = *(const float2*)&pp[4],  q3 = *(const float2*)&pp[6];
            float2 q4 = *(const float2*)&pp[8],  q5 = *(const float2*)&pp[10];
            float2 q6 = *(const float2*)&pp[12], q7 = *(const float2*)&pp[14];
            float2 q8 = *(const float2*)&pp[16], q9 = *(const float2*)&pp[18];
            float2 qa = *(const float2*)&pp[20], qb = *(const float2*)&pp[22];
            float rsum = ((q0.x+q0.y)+(q1.x+q1.y)) + ((q2.x+q2.y)+(q3.x+q3.y));
            float zsum = ((q4.x+q4.y)+(q5.x+q5.y)) + ((q6.x+q6.y)+(q7.x+q7.y));
            float nsum = ((q8.x+q8.y)+(q9.x+q9.y)) + ((qa.x+qa.y)+(qb.x+qb.y));
            float hprev = hp[b2 * HD + jG2];

            float r  = 1.f / (1.f + __expf(-(pr + rsum + bhr)));
            float z  = 1.f / (1.f + __expf(-(pz + zsum + bhz)));
            float nx = pn + r * (nsum + bhn);
            float e2 = __expf(-2.f * nx);
            float n  = 2.f / (1.f + e2) - 1.f;          // tanh, inf-safe
            float hnew = fmaf(z, hprev - n, n);         // (1-z)*n + z*h

            if (pd >= 0) out[((size_t)pd * BS + bG2) * HD + jG2] = hnew;
            pr = nr; pz = nz; pn = nn2; pd = nd;

            if (s + 1 < SQ) {
                // push hnew into every cluster CTA's next-parity buffer
                unsigned laddr = smbase +
                    ((unsigned)((1 - p) * SM_HBUF + b2 * HD + jG2) << 2);
                #pragma unroll
                for (int i = 0; i < CLU; i++) {
                    unsigned r16 = (rank + (unsigned)i) & (CLU - 1);
                    dsmem_store(laddr, r16, hnew);
                }
            }
        }

        // ---- cluster barrier: release our stores / acquire peers' ----
        if (s + 1 < SQ) {
            asm volatile("barrier.cluster.arrive.aligned;" ::: "memory");
            asm volatile("barrier.cluster.wait.aligned;"   ::: "memory");
        }
    }
}

// ------------------- launch -------------------------------------------------
extern "C" void kernel_launch(void* const* d_in, const int* in_sizes, int n_in,
                              void* d_out, int out_size) {
    const int*   tokens = (const int*)d_in[0];
    const float* emb    = (const float*)d_in[1];
    const float* w_ih   = (const float*)d_in[2];
    const float* w_hh   = (const float*)d_in[3];
    const float* b_ih   = (const float*)d_in[4];
    const float* b_hh   = (const float*)d_in[5];
    float* out = (float*)d_out;

    cudaFuncSetAttribute(gru_kernel,
                         cudaFuncAttributeMaxDynamicSharedMemorySize, GRU_SMEM);
    cudaFuncSetAttribute(gru_kernel,
                         cudaFuncAttributeNonPortableClusterSizeAllowed, 1);

    gtab_kernel<<<dim3(G3 / 128, VB / 128), 256>>>(emb, w_ih, b_ih, tokens);

    cudaLaunchConfig_t cfg = {};
    cfg.gridDim = dim3(NCTA, 1, 1);
    cfg.blockDim = dim3(256, 1, 1);
    cfg.dynamicSmemBytes = GRU_SMEM;
    cudaLaunchAttribute attrs[1];
    attrs[0].id = cudaLaunchAttributeClusterDimension;
    attrs[0].val.clusterDim.x = CLU;
    attrs[0].val.clusterDim.y = 1;
    attrs[0].val.clusterDim.z = 1;
    cfg.attrs = attrs;
    cfg.numAttrs = 1;
    cudaLaunchKernelEx(&cfg, gru_kernel, tokens, w_hh, b_hh, out);
}

// round 14
// speedup vs baseline: 1.1825x; 1.1825x over previous
#include <cuda_runtime.h>

#define SQ   1024
#define BS   64
#define HD   512
#define ED   256
#define VB   32000
#define G3   1536
#define EOSV 2
#define NEOS 32

#define NPAIR 4            // CTA pairs-of-batch-groups: pair owns 16 batches
#define NRG   32           // j groups (16 h-dims each)
#define NCTA  (NPAIR*NRG)  // 128 CTAs, 1/SM; A/B halves pipelined in-CTA

#define PSTR 26            // psum row stride (floats): 24 used, bank-clean
#define SM_HA    (8*HD)                       // 4096 fl
#define SM_HB    (8*HD)
#define SM_PSUM  (128*PSTR)                   // 3328 fl
#define GRU_SMEM ((SM_HA + SM_HB + SM_PSUM) * 4)   // 46080 B

typedef unsigned long long u64;

// ------------------- device scratch (static only; no allocs) ----------------
__device__ float    g_Gtab[(size_t)VB * G3];   // ~197MB input-projection table
__device__ float    g_h[2][BS * HD];           // double-buffered hidden state
__device__ int      g_dest[SQ * BS];           // EOS compaction slot or -1
__device__ unsigned g_ctr[NPAIR * 2 * 64];     // [pair][half] counters, 256B apart

// ------------------- packed f32x2 helpers ----------------------------------
__device__ __forceinline__ u64 ffma2(u64 a, u64 b, u64 c) {
    u64 d;
    asm("fma.rn.f32x2 %0, %1, %2, %3;" : "=l"(d) : "l"(a), "l"(b), "l"(c));
    return d;
}
__device__ __forceinline__ float2 unpack2(u64 v) {
    float2 f;
    asm("mov.b64 {%0, %1}, %2;" : "=f"(f.x), "=f"(f.y) : "l"(v));
    return f;
}
__device__ __forceinline__ float hsum2(u64 v) {
    float2 f = unpack2(v);
    return f.x + f.y;
}
__device__ __forceinline__ u64 bcast2(float x) {
    u64 d;
    asm("mov.b64 %0, {%1, %1};" : "=l"(d) : "f"(x));
    return d;
}
__device__ __forceinline__ unsigned ld_acq(const unsigned* p) {
    unsigned v;
    asm volatile("ld.acquire.gpu.global.u32 %0, [%1];" : "=r"(v) : "l"(p));
    return v;
}
__device__ __forceinline__ void red_release_add(unsigned* p, unsigned v) {
    asm volatile("red.release.gpu.global.add.u32 [%0], %1;" :: "l"(p), "r"(v) : "memory");
}

// ------------------- Gtab GEMM (+fused prep): G = w_ih * emb^T + b_ih ------
__global__ void __launch_bounds__(256) gtab_kernel(
    const float* __restrict__ emb,
    const float* __restrict__ w_ih,
    const float* __restrict__ b_ih,
    const int*   __restrict__ tokens)
{
    // ---- fused prep: h0, counters, EOS scan (first 64 flat CTAs, warp 0) ----
    int fid = blockIdx.y * 12 + blockIdx.x;
    if (fid < BS && threadIdx.x < 32) {
        int b = fid, t = threadIdx.x;
        if (fid == 0 && t < NPAIR * 2) g_ctr[t * 64] = 0u;
        for (int i = t; i < HD; i += 32) g_h[0][b * HD + i] = 0.f;
        int s0 = t * 32;
        int cnt = 0;
        #pragma unroll
        for (int i = 0; i < 32; i++) cnt += (tokens[b * SQ + s0 + i] == EOSV);
        int pre = cnt;
        #pragma unroll
        for (int m = 1; m < 32; m <<= 1) {
            int v = __shfl_up_sync(0xffffffffu, pre, m);
            if (t >= m) pre += v;
        }
        pre -= cnt;
        int k = pre;
        #pragma unroll
        for (int i = 0; i < 32; i++) {
            int s = s0 + i;
            bool e = (tokens[b * SQ + s] == EOSV);
            g_dest[s * BS + b] = (e && k < NEOS) ? k : -1;
            k += e;
        }
    }

    // ---- GEMM: 128x128 tile, 16-k steps, 8x8 microtile, f32x2 ----
    __shared__ float A_sT[16 * 132];
    __shared__ float B_sT[16 * 132];

    int tid = threadIdx.x;
    int tx = tid & 15, ty = tid >> 4;
    int g0 = blockIdx.x * 128;
    int t0 = blockIdx.y * 128;

    u64 acc[8][4];
    #pragma unroll
    for (int i = 0; i < 8; i++)
        #pragma unroll
        for (int j = 0; j < 4; j++) acc[i][j] = 0ull;

    for (int k0 = 0; k0 < ED; k0 += 16) {
        __syncthreads();
        #pragma unroll
        for (int i = 0; i < 2; i++) {
            int ff  = tid + i * 256;
            int row = ff >> 2;
            int c4  = (ff & 3) * 4;
            float4 va = *(const float4*)&emb[(size_t)(t0 + row) * ED + k0 + c4];
            A_sT[(c4 + 0) * 132 + row] = va.x;
            A_sT[(c4 + 1) * 132 + row] = va.y;
            A_sT[(c4 + 2) * 132 + row] = va.z;
            A_sT[(c4 + 3) * 132 + row] = va.w;
            float4 vb = *(const float4*)&w_ih[(size_t)(g0 + row) * ED + k0 + c4];
            B_sT[(c4 + 0) * 132 + row] = vb.x;
            B_sT[(c4 + 1) * 132 + row] = vb.y;
            B_sT[(c4 + 2) * 132 + row] = vb.z;
            B_sT[(c4 + 3) * 132 + row] = vb.w;
        }
        __syncthreads();
        #pragma unroll
        for (int k = 0; k < 16; k++) {
            float4 a0 = *(const float4*)&A_sT[k * 132 + ty * 4];
            float4 a1 = *(const float4*)&A_sT[k * 132 + 64 + ty * 4];
            u64 b0x = *(const u64*)&B_sT[k * 132 + tx * 4];
            u64 b0y = *(const u64*)&B_sT[k * 132 + tx * 4 + 2];
            u64 b1x = *(const u64*)&B_sT[k * 132 + 64 + tx * 4];
            u64 b1y = *(const u64*)&B_sT[k * 132 + 64 + tx * 4 + 2];
            float af[8] = {a0.x, a0.y, a0.z, a0.w, a1.x, a1.y, a1.z, a1.w};
            #pragma unroll
            for (int i = 0; i < 8; i++) {
                u64 ap = bcast2(af[i]);
                acc[i][0] = ffma2(ap, b0x, acc[i][0]);
                acc[i][1] = ffma2(ap, b0y, acc[i][1]);
                acc[i][2] = ffma2(ap, b1x, acc[i][2]);
                acc[i][3] = ffma2(ap, b1y, acc[i][3]);
            }
        }
    }

    float4 bia0 = *(const float4*)&b_ih[g0 + tx * 4];
    float4 bia1 = *(const float4*)&b_ih[g0 + 64 + tx * 4];
    #pragma unroll
    for (int i = 0; i < 8; i++) {
        int trow = t0 + (i >> 2) * 64 + ty * 4 + (i & 3);
        float2 c0 = unpack2(acc[i][0]);
        float2 c1 = unpack2(acc[i][1]);
        float2 c2 = unpack2(acc[i][2]);
        float2 c3 = unpack2(acc[i][3]);
        float4 o0 = make_float4(c0.x + bia0.x, c0.y + bia0.y, c1.x + bia0.z, c1.y + bia0.w);
        float4 o1 = make_float4(c2.x + bia1.x, c2.y + bia1.y, c3.x + bia1.z, c3.y + bia1.w);
        *(float4*)&g_Gtab[(size_t)trow * G3 + g0 + tx * 4]      = o0;
        *(float4*)&g_Gtab[(size_t)trow * G3 + g0 + 64 + tx * 4] = o1;
    }
}

// ------------------- persistent GRU recurrence ------------------------------
// 128 CTAs (4 pairs x 32 rg), 256 threads, 1/SM. IN-CTA PIPELINING of two
// independent recurrences: half A = batches pair*16..+7, half B = +8..+15,
// each with its own 32-CTA barrier. Program order alternates A-compute and
// B-compute, so each barrier's detect+spread window resolves UNDER the other
// half's ~2000-cycle compute — deterministically, unlike R9's arbiter-based
// co-resident-CTA overlap. W_hh regs (1 j x 3 gates x 32 K = 48 u64) are
// shared by both halves.
__global__ void __launch_bounds__(256, 1) gru_kernel(
    const int*   __restrict__ tokens,
    const float* __restrict__ w_hh,
    const float* __restrict__ b_hh,
    float*       __restrict__ out)
{
    extern __shared__ float sm[];
    float* hA   = sm;                        // [8][512]
    float* hB   = sm + SM_HA;                // [8][512]
    float* psum = sm + SM_HA + SM_HB;        // [128][PSTR]

    int tid = threadIdx.x;
    int bid = blockIdx.x;
    int pair = bid >> 5, rg = bid & 31;
    int ks = tid >> 4;          // 0..15  (32-elem k slice)
    int jl = tid & 15;          // broadcast lanes
    int jG = rg * 16 + jl;

    // one-time W_hh register slice: 3 gates x 32 K, rotated float4 order
    u64 wr[16], wz[16], wn[16];
    #pragma unroll
    for (int i4 = 0; i4 < 8; i4++) {
        int col = ks * 32 + ((i4 + 4 * ks) & 7) * 4;
        const float* r0 = &w_hh[(size_t)(0 * HD + jG) * HD + col];
        const float* r1 = &w_hh[(size_t)(1 * HD + jG) * HD + col];
        const float* r2 = &w_hh[(size_t)(2 * HD + jG) * HD + col];
        wr[2*i4] = *(const u64*)r0;  wr[2*i4+1] = *(const u64*)(r0 + 2);
        wz[2*i4] = *(const u64*)r1;  wz[2*i4+1] = *(const u64*)(r1 + 2);
        wn[2*i4] = *(const u64*)r2;  wn[2*i4+1] = *(const u64*)(r2 + 2);
    }

    // phase-2 / prefetch role: lower 128 threads own half A's (b,j) pairs,
    // upper 128 own half B's.
    int hlf  = tid >> 7;                      // 0 = A, 1 = B
    int lt   = tid & 127;
    int bloc = lt >> 4;                       // 0..7
    int jloc = lt & 15;
    int bG2  = pair * 16 + hlf * 8 + bloc;
    int jG2  = rg * 16 + jloc;
    float bhr = b_hh[jG2], bhz = b_hh[HD + jG2], bhn = b_hh[2 * HD + jG2];

    int tok0 = __ldg(&tokens[bG2 * SQ]);
    const float* gp0 = &g_Gtab[(size_t)tok0 * G3 + jG2];
    float pr = __ldcs(gp0), pz = __ldcs(gp0 + HD), pn = __ldcs(gp0 + 2 * HD);
    int pd = __ldg(&g_dest[bG2]);

    bool store_lane = ((ks & 1) == 0);
    int  slot = ks >> 1;                      // 0..7

    unsigned* ctrA = &g_ctr[(pair * 2 + 0) * 64];
    unsigned* ctrB = &g_ctr[(pair * 2 + 1) * 64];

    for (int s = 0; s < SQ; s++) {
        #pragma unroll 2
        for (int h = 0; h < 2; h++) {         // h=0: half A, h=1: half B
            unsigned* ctr = h ? ctrB : ctrA;
            float* hs = h ? hB : hA;
            int bbase = pair * 16 + h * 8;

            // ---- wait for this half's producers (resolved under the other
            //      half's compute); skip at s=0 ----
            if (s > 0) {
                if (tid == 0) {
                    unsigned tgt = 32u * (unsigned)s;
                    while (ld_acq(ctr) < tgt) { }
                }
            }
            __syncthreads();

            // ---- load h(s): 8 rows x 512 = 1024 f4 -> 4 per thread ----
            {
                const float* hsrc = &g_h[s & 1][bbase * HD];
                float4 hv[4];
                #pragma unroll
                for (int i = 0; i < 4; i++) {
                    int f = tid + i * 256;
                    hv[i] = __ldcg((const float4*)&hsrc[(f >> 7) * HD + (f & 127) * 4]);
                }
                #pragma unroll
                for (int i = 0; i < 4; i++) {
                    int f = tid + i * 256;
                    *(float4*)&hs[(f >> 7) * HD + (f & 127) * 4] = hv[i];
                }
            }
            __syncthreads();

            // ---- phase 1: all 256 threads, 2 batches per pass (6 chains) ----
            #pragma unroll 2
            for (int p = 0; p < 4; p++) {
                int b0 = 2 * p, b1 = 2 * p + 1;
                const float* hb0 = &hs[b0 * HD];
                const float* hb1 = &hs[b1 * HD];
                u64 a0r = 0, a0z = 0, a0n = 0, a1r = 0, a1z = 0, a1n = 0;
                #pragma unroll
                for (int i4 = 0; i4 < 8; i4++) {
                    int col = ks * 32 + ((i4 + 4 * ks) & 7) * 4;
                    ulonglong2 h0 = *(const ulonglong2*)&hb0[col];
                    ulonglong2 h1 = *(const ulonglong2*)&hb1[col];
                    a0r = ffma2(wr[2*i4], h0.x, a0r);
                    a1r = ffma2(wr[2*i4], h1.x, a1r);
                    a0z = ffma2(wz[2*i4], h0.x, a0z);
                    a1z = ffma2(wz[2*i4], h1.x, a1z);
                    a0n = ffma2(wn[2*i4], h0.x, a0n);
                    a1n = ffma2(wn[2*i4], h1.x, a1n);
                    a0r = ffma2(wr[2*i4+1], h0.y, a0r);
                    a1r = ffma2(wr[2*i4+1], h1.y, a1r);
                    a0z = ffma2(wz[2*i4+1], h0.y, a0z);
                    a1z = ffma2(wz[2*i4+1], h1.y, a1z);
                    a0n = ffma2(wn[2*i4+1], h0.y, a0n);
                    a1n = ffma2(wn[2*i4+1], h1.y, a1n);
                }
                float v0r = hsum2(a0r), v0z = hsum2(a0z), v0n = hsum2(a0n);
                float v1r = hsum2(a1r), v1z = hsum2(a1z), v1n = hsum2(a1n);
                // combine ks-pair (same jl, lane^16)
                v0r += __shfl_xor_sync(0xffffffffu, v0r, 16);
                v0z += __shfl_xor_sync(0xffffffffu, v0z, 16);
                v0n += __shfl_xor_sync(0xffffffffu, v0n, 16);
                v1r += __shfl_xor_sync(0xffffffffu, v1r, 16);
                v1z += __shfl_xor_sync(0xffffffffu, v1z, 16);
                v1n += __shfl_xor_sync(0xffffffffu, v1n, 16);
                if (store_lane) {
                    float* p0 = &psum[(b0 * 16 + jl) * PSTR];
                    float* p1 = &psum[(b1 * 16 + jl) * PSTR];
                    p0[slot] = v0r;  p0[8 + slot] = v0z;  p0[16 + slot] = v0n;
                    p1[slot] = v1r;  p1[8 + slot] = v1z;  p1[16 + slot] = v1n;
                }
            }

            // ---- this half's threads prefetch their gi(s+1)/dest(s+1) ----
            float nr = 0.f, nz = 0.f, nn2 = 0.f;
            int nd = -1;
            if (hlf == h && s + 1 < SQ) {
                int tk = __ldg(&tokens[bG2 * SQ + s + 1]);
                const float* gq = &g_Gtab[(size_t)tk * G3 + jG2];
                nr  = __ldcs(gq);
                nz  = __ldcs(gq + HD);
                nn2 = __ldcs(gq + 2 * HD);
                nd  = __ldg(&g_dest[(s + 1) * BS + bG2]);
            }
            __syncthreads();

            // ---- phase 2: this half's 128 threads reduce + gates + store ----
            if (hlf == h) {
                const float* pp = &psum[lt * PSTR];
                float2 q0 = *(const float2*)&pp[0],  q1 = *(const float2*)&pp[2];
                float2 q2 = *(const float2*)&pp[4],  q3 = *(const float2*)&pp[6];
                float2 q4 = *(const float2*)&pp[8],  q5 = *(const float2*)&pp[10];
                float2 q6 = *(const float2*)&pp[12], q7 = *(const float2*)&pp[14];
                float2 q8 = *(const float2*)&pp[16], q9 = *(const float2*)&pp[18];
                float2 qa = *(const float2*)&pp[20], qb = *(const float2*)&pp[22];
                float rsum = ((q0.x+q0.y)+(q1.x+q1.y)) + ((q2.x+q2.y)+(q3.x+q3.y));
                float zsum = ((q4.x+q4.y)+(q5.x+q5.y)) + ((q6.x+q6.y)+(q7.x+q7.y));
                float nsum = ((q8.x+q8.y)+(q9.x+q9.y)) + ((qa.x+qa.y)+(qb.x+qb.y));
                float hprev = hs[bloc * HD + jG2];

                float r  = 1.f / (1.f + __expf(-(pr + rsum + bhr)));
                float z  = 1.f / (1.f + __expf(-(pz + zsum + bhz)));
                float nx = pn + r * (nsum + bhn);
                float e2 = __expf(-2.f * nx);
                float n  = 2.f / (1.f + e2) - 1.f;          // tanh, inf-safe
                float hnew = fmaf(z, hprev - n, n);         // (1-z)*n + z*h

                g_h[(s + 1) & 1][bG2 * HD + jG2] = hnew;
                if (pd >= 0) out[((size_t)pd * BS + bG2) * HD + jG2] = hnew;
                pr = nr; pz = nz; pn = nn2; pd = nd;
            }

            // ---- arrive (orders hnew stores first) ----
            __syncthreads();
            if (s + 1 < SQ && tid == 0) red_release_add(ctr, 1u);
        }
    }
}

// ------------------- launch -------------------------------------------------
extern "C" void kernel_launch(void* const* d_in, const int* in_sizes, int n_in,
                              void* d_out, int out_size) {
    const int*   tokens = (const int*)d_in[0];
    const float* emb    = (const float*)d_in[1];
    const float* w_ih   = (const float*)d_in[2];
    const float* w_hh   = (const float*)d_in[3];
    const float* b_ih   = (const float*)d_in[4];
    const float* b_hh   = (const float*)d_in[5];
    float* out = (float*)d_out;

    cudaFuncSetAttribute(gru_kernel,
                         cudaFuncAttributeMaxDynamicSharedMemorySize, GRU_SMEM);

    gtab_kernel<<<dim3(G3 / 128, VB / 128), 256>>>(emb, w_ih, b_ih, tokens);
    gru_kernel<<<NCTA, 256, GRU_SMEM>>>(tokens, w_hh, b_hh, out);
}

// round 15
// speedup vs baseline: 1.8033x; 1.5249x over previous
#include <cuda_runtime.h>

#define SQ   1024
#define BS   64
#define HD   512
#define ED   256
#define VB   32000
#define G3   1536
#define EOSV 2
#define NEOS 32

#define NBG  8            // batch groups (8 rows each)
#define NRG  32           // j groups (16 h-dims each)
#define NCTA (NBG*NRG)    // 256 CTAs, 2 per SM (cross-bg stall overlap)

#define STAGGER_CYC 3000ull   // anti-phase head start for bgs 4-7

#define PSTR 14           // psum row stride (floats), 12 used
#define SM_H      (8*HD)
#define SM_PSUM   (8*16*PSTR)
#define GRU_SMEM  ((SM_H + SM_PSUM) * 4)

typedef unsigned long long u64;

// ------------------- device scratch (static only; no allocs) ----------------
__device__ float    g_Gtab[(size_t)VB * G3];   // ~197MB input-projection table
__device__ float    g_h[2][BS * HD];           // double-buffered hidden state
__device__ int      g_dest[SQ * BS];           // EOS compaction slot or -1
__device__ unsigned g_ctr[NBG * 64];           // barrier counters, 256B stride

// ------------------- packed f32x2 helpers ----------------------------------
__device__ __forceinline__ u64 ffma2(u64 a, u64 b, u64 c) {
    u64 d;
    asm("fma.rn.f32x2 %0, %1, %2, %3;" : "=l"(d) : "l"(a), "l"(b), "l"(c));
    return d;
}
__device__ __forceinline__ float2 unpack2(u64 v) {
    float2 f;
    asm("mov.b64 {%0, %1}, %2;" : "=f"(f.x), "=f"(f.y) : "l"(v));
    return f;
}
__device__ __forceinline__ float hsum2(u64 v) {
    float2 f = unpack2(v);
    return f.x + f.y;
}
__device__ __forceinline__ u64 bcast2(float x) {
    u64 d;
    asm("mov.b64 %0, {%1, %1};" : "=l"(d) : "f"(x));
    return d;
}
__device__ __forceinline__ unsigned ld_acq(const unsigned* p) {
    unsigned v;
    asm volatile("ld.acquire.gpu.global.u32 %0, [%1];" : "=r"(v) : "l"(p));
    return v;
}
__device__ __forceinline__ void red_release_add(unsigned* p, unsigned v) {
    asm volatile("red.release.gpu.global.add.u32 [%0], %1;" :: "l"(p), "r"(v) : "memory");
}

// ------------------- Gtab GEMM (+fused prep): G = w_ih * emb^T + b_ih ------
__global__ void __launch_bounds__(256) gtab_kernel(
    const float* __restrict__ emb,
    const float* __restrict__ w_ih,
    const float* __restrict__ b_ih,
    const int*   __restrict__ tokens)
{
    // ---- fused prep: h0, counters, EOS scan (first 64 flat CTAs, warp 0) ----
    int fid = blockIdx.y * 12 + blockIdx.x;
    if (fid < BS && threadIdx.x < 32) {
        int b = fid, t = threadIdx.x;
        if (fid == 0 && t < NBG) g_ctr[t * 64] = 0u;
        for (int i = t; i < HD; i += 32) g_h[0][b * HD + i] = 0.f;
        int s0 = t * 32;
        int cnt = 0;
        #pragma unroll
        for (int i = 0; i < 32; i++) cnt += (tokens[b * SQ + s0 + i] == EOSV);
        int pre = cnt;
        #pragma unroll
        for (int m = 1; m < 32; m <<= 1) {
            int v = __shfl_up_sync(0xffffffffu, pre, m);
            if (t >= m) pre += v;
        }
        pre -= cnt;
        int k = pre;
        #pragma unroll
        for (int i = 0; i < 32; i++) {
            int s = s0 + i;
            bool e = (tokens[b * SQ + s] == EOSV);
            g_dest[s * BS + b] = (e && k < NEOS) ? k : -1;
            k += e;
        }
    }

    // ---- GEMM: 128x128 tile, 16-k steps, 8x8 microtile, f32x2 ----
    __shared__ float A_sT[16 * 132];
    __shared__ float B_sT[16 * 132];

    int tid = threadIdx.x;
    int tx = tid & 15, ty = tid >> 4;
    int g0 = blockIdx.x * 128;
    int t0 = blockIdx.y * 128;

    u64 acc[8][4];
    #pragma unroll
    for (int i = 0; i < 8; i++)
        #pragma unroll
        for (int j = 0; j < 4; j++) acc[i][j] = 0ull;

    for (int k0 = 0; k0 < ED; k0 += 16) {
        __syncthreads();
        #pragma unroll
        for (int i = 0; i < 2; i++) {
            int ff  = tid + i * 256;
            int row = ff >> 2;
            int c4  = (ff & 3) * 4;
            float4 va = *(const float4*)&emb[(size_t)(t0 + row) * ED + k0 + c4];
            A_sT[(c4 + 0) * 132 + row] = va.x;
            A_sT[(c4 + 1) * 132 + row] = va.y;
            A_sT[(c4 + 2) * 132 + row] = va.z;
            A_sT[(c4 + 3) * 132 + row] = va.w;
            float4 vb = *(const float4*)&w_ih[(size_t)(g0 + row) * ED + k0 + c4];
            B_sT[(c4 + 0) * 132 + row] = vb.x;
            B_sT[(c4 + 1) * 132 + row] = vb.y;
            B_sT[(c4 + 2) * 132 + row] = vb.z;
            B_sT[(c4 + 3) * 132 + row] = vb.w;
        }
        __syncthreads();
        #pragma unroll
        for (int k = 0; k < 16; k++) {
            float4 a0 = *(const float4*)&A_sT[k * 132 + ty * 4];
            float4 a1 = *(const float4*)&A_sT[k * 132 + 64 + ty * 4];
            u64 b0x = *(const u64*)&B_sT[k * 132 + tx * 4];
            u64 b0y = *(const u64*)&B_sT[k * 132 + tx * 4 + 2];
            u64 b1x = *(const u64*)&B_sT[k * 132 + 64 + tx * 4];
            u64 b1y = *(const u64*)&B_sT[k * 132 + 64 + tx * 4 + 2];
            float af[8] = {a0.x, a0.y, a0.z, a0.w, a1.x, a1.y, a1.z, a1.w};
            #pragma unroll
            for (int i = 0; i < 8; i++) {
                u64 ap = bcast2(af[i]);
                acc[i][0] = ffma2(ap, b0x, acc[i][0]);
                acc[i][1] = ffma2(ap, b0y, acc[i][1]);
                acc[i][2] = ffma2(ap, b1x, acc[i][2]);
                acc[i][3] = ffma2(ap, b1y, acc[i][3]);
            }
        }
    }

    float4 bia0 = *(const float4*)&b_ih[g0 + tx * 4];
    float4 bia1 = *(const float4*)&b_ih[g0 + 64 + tx * 4];
    #pragma unroll
    for (int i = 0; i < 8; i++) {
        int trow = t0 + (i >> 2) * 64 + ty * 4 + (i & 3);
        float2 c0 = unpack2(acc[i][0]);
        float2 c1 = unpack2(acc[i][1]);
        float2 c2 = unpack2(acc[i][2]);
        float2 c3 = unpack2(acc[i][3]);
        float4 o0 = make_float4(c0.x + bia0.x, c0.y + bia0.y, c1.x + bia0.z, c1.y + bia0.w);
        float4 o1 = make_float4(c2.x + bia1.x, c2.y + bia1.y, c3.x + bia1.z, c3.y + bia1.w);
        *(float4*)&g_Gtab[(size_t)trow * G3 + g0 + tx * 4]      = o0;
        *(float4*)&g_Gtab[(size_t)trow * G3 + g0 + 64 + tx * 4] = o1;
    }
}

// ------------------- persistent GRU recurrence ------------------------------
// 256 CTAs (8 bg x 32 rg), 128 threads, 2 CTAs/SM from different bgs
// (scheduler-based stall overlap = R9/R10, the only structure that won).
// R14 tweaks: (1) EARLY RELEASE — arrive fires right after hnew STG + sync,
// with the EOS out[] store and prefetch-register rotation moved AFTER it so
// they overlap the poll; (2) DUAL-SAMPLE POLL — two back-to-back acquire
// loads per iteration halve the detect quantum.
__global__ void __launch_bounds__(128, 2) gru_kernel(
    const int*   __restrict__ tokens,
    const float* __restrict__ w_hh,
    const float* __restrict__ b_hh,
    float*       __restrict__ out)
{
    extern __shared__ float sm[];
    float (*h_s)[HD] = (float(*)[HD])sm;      // [8][512]  16KB
    float* psum = sm + SM_H;                   // [8*16][PSTR]

    int tid = threadIdx.x;
    int bid = blockIdx.x;
    int bg = bid >> 5, rg = bid & 31;
    int ks = tid >> 4;          // 0..7   (64-elem k slice)
    int jl = tid & 15;          // broadcast lanes
    int jG = rg * 16 + jl;

    // one-time W_hh register slice: 3 gates x 64 elems, rotated float4 order
    u64 wr[32], wz[32], wn[32];
    #pragma unroll
    for (int i4 = 0; i4 < 16; i4++) {
        int col = ks * 64 + ((i4 + 4 * ks) & 15) * 4;
        const float* r0 = &w_hh[(size_t)(0 * HD + jG) * HD + col];
        const float* r1 = &w_hh[(size_t)(1 * HD + jG) * HD + col];
        const float* r2 = &w_hh[(size_t)(2 * HD + jG) * HD + col];
        wr[2 * i4] = *(const u64*)r0;  wr[2 * i4 + 1] = *(const u64*)(r0 + 2);
        wz[2 * i4] = *(const u64*)r1;  wz[2 * i4 + 1] = *(const u64*)(r1 + 2);
        wn[2 * i4] = *(const u64*)r2;  wn[2 * i4 + 1] = *(const u64*)(r2 + 2);
    }

    // phase-2 / prefetch role: one (batch, j) per thread
    int bl2 = tid >> 4;                       // 0..7
    int bG2 = bg * 8 + bl2;
    int jG2 = jG;
    float bhr = b_hh[jG2], bhz = b_hh[HD + jG2], bhn = b_hh[2 * HD + jG2];

    int tok0 = __ldg(&tokens[bG2 * SQ]);
    const float* gp0 = &g_Gtab[(size_t)tok0 * G3 + jG2];
    float pr = __ldcs(gp0), pz = __ldcs(gp0 + HD), pn = __ldcs(gp0 + 2 * HD);
    int pd = __ldg(&g_dest[bG2]);

    bool store_lane = ((ks & 1) == 0);
    int  slot = ks >> 1;                      // 0..3

    // ---- anti-phase stagger: bgs 4-7 start half a step late ----
    if (bg >= 4) {
        unsigned long long tc0 = clock64();
        while (clock64() - tc0 < STAGGER_CYC) { }
    }
    __syncthreads();

    for (int s = 0; s < SQ; s++) {
        // ---- load h(s): 8 rows x 512 = 1024 float4 -> 8 per thread ----
        {
            const float* hsrc = &g_h[s & 1][bg * 8 * HD];
            float4 hv[8];
            #pragma unroll
            for (int i = 0; i < 8; i++) {
                int f = tid + i * 128;
                hv[i] = __ldcg((const float4*)&hsrc[(f >> 7) * HD + (f & 127) * 4]);
            }
            #pragma unroll
            for (int i = 0; i < 8; i++) {
                int f = tid + i * 128;
                *(float4*)&h_s[f >> 7][(f & 127) * 4] = hv[i];
            }
        }
        __syncthreads();

        // ---- phase 1: split-K partials, 2 batches per pass (6 chains) ----
        #pragma unroll 2
        for (int p = 0; p < 4; p++) {
            int b0 = 2 * p, b1 = 2 * p + 1;
            u64 a0r = 0, a0z = 0, a0n = 0, a1r = 0, a1z = 0, a1n = 0;
            #pragma unroll
            for (int i4 = 0; i4 < 16; i4++) {
                int col = ks * 64 + ((i4 + 4 * ks) & 15) * 4;
                ulonglong2 h0 = *(const ulonglong2*)&h_s[b0][col];
                ulonglong2 h1 = *(const ulonglong2*)&h_s[b1][col];
                a0r = ffma2(wr[2 * i4], h0.x, a0r);
                a1r = ffma2(wr[2 * i4], h1.x, a1r);
                a0z = ffma2(wz[2 * i4], h0.x, a0z);
                a1z = ffma2(wz[2 * i4], h1.x, a1z);
                a0n = ffma2(wn[2 * i4], h0.x, a0n);
                a1n = ffma2(wn[2 * i4], h1.x, a1n);
                a0r = ffma2(wr[2 * i4 + 1], h0.y, a0r);
                a1r = ffma2(wr[2 * i4 + 1], h1.y, a1r);
                a0z = ffma2(wz[2 * i4 + 1], h0.y, a0z);
                a1z = ffma2(wz[2 * i4 + 1], h1.y, a1z);
                a0n = ffma2(wn[2 * i4 + 1], h0.y, a0n);
                a1n = ffma2(wn[2 * i4 + 1], h1.y, a1n);
            }
            float v0r = hsum2(a0r), v0z = hsum2(a0z), v0n = hsum2(a0n);
            float v1r = hsum2(a1r), v1z = hsum2(a1z), v1n = hsum2(a1n);
            // combine ks-pair (same jl, lane^16)
            v0r += __shfl_xor_sync(0xffffffffu, v0r, 16);
            v0z += __shfl_xor_sync(0xffffffffu, v0z, 16);
            v0n += __shfl_xor_sync(0xffffffffu, v0n, 16);
            v1r += __shfl_xor_sync(0xffffffffu, v1r, 16);
            v1z += __shfl_xor_sync(0xffffffffu, v1z, 16);
            v1n += __shfl_xor_sync(0xffffffffu, v1n, 16);
            if (store_lane) {
                float* p0 = &psum[(b0 * 16 + jl) * PSTR];
                float* p1 = &psum[(b1 * 16 + jl) * PSTR];
                p0[slot] = v0r;  p0[4 + slot] = v0z;  p0[8 + slot] = v0n;
                p1[slot] = v1r;  p1[4 + slot] = v1z;  p1[8 + slot] = v1n;
            }
        }

        // ---- prefetch gi(s+1)/dest(s+1): hidden under sync + next barrier ----
        float nr = 0.f, nz = 0.f, nn2 = 0.f;
        int nd = -1;
        if (s + 1 < SQ) {
            int tk = __ldg(&tokens[bG2 * SQ + s + 1]);
            const float* gq = &g_Gtab[(size_t)tk * G3 + jG2];
            nr  = __ldcs(gq);
            nz  = __ldcs(gq + HD);
            nn2 = __ldcs(gq + 2 * HD);
            nd  = __ldg(&g_dest[(s + 1) * BS + bG2]);
        }
        __syncthreads();

        // ---- phase 2a: reduce, gates, hnew -> g_h store (critical path) ----
        float hnew;
        {
            const float* pp = &psum[tid * PSTR];
            float2 q0 = *(const float2*)&pp[0], q1 = *(const float2*)&pp[2];
            float2 q2 = *(const float2*)&pp[4], q3 = *(const float2*)&pp[6];
            float2 q4 = *(const float2*)&pp[8], q5 = *(const float2*)&pp[10];
            float rsum = (q0.x + q0.y) + (q1.x + q1.y);
            float zsum = (q2.x + q2.y) + (q3.x + q3.y);
            float nsum = (q4.x + q4.y) + (q5.x + q5.y);
            float hprev = h_s[bl2][jG2];

            float r  = 1.f / (1.f + __expf(-(pr + rsum + bhr)));
            float z  = 1.f / (1.f + __expf(-(pz + zsum + bhz)));
            float nx = pn + r * (nsum + bhn);
            float e2 = __expf(-2.f * nx);
            float n  = 2.f / (1.f + e2) - 1.f;          // tanh, inf-safe
            hnew = fmaf(z, hprev - n, n);               // (1-z)*n + z*h

            g_h[(s + 1) & 1][bG2 * HD + jG2] = hnew;
        }

        // ---- EARLY RELEASE: arrive as soon as hnew stores are ordered ----
        if (s + 1 < SQ) {
            __syncthreads();                    // all 128 hnew STGs issued
            if (tid == 0) red_release_add(&g_ctr[bg * 64], 1u);
        }

        // ---- phase 2b (overlaps the poll): EOS store + register rotation ----
        if (pd >= 0) out[((size_t)pd * BS + bG2) * HD + jG2] = hnew;
        pr = nr; pz = nz; pn = nn2; pd = nd;

        // ---- detect: tid0 dual-sample poll, then block wake ----
        if (s + 1 < SQ) {
            if (tid == 0) {
                unsigned tgt = 32u * (unsigned)(s + 1);
                for (;;) {
                    unsigned a = ld_acq(&g_ctr[bg * 64]);
                    unsigned b = ld_acq(&g_ctr[bg * 64]);
                    if (a >= tgt || b >= tgt) break;
                }
            }
            __syncthreads();
        }
    }
}

// ------------------- launch -------------------------------------------------
extern "C" void kernel_launch(void* const* d_in, const int* in_sizes, int n_in,
                              void* d_out, int out_size) {
    const int*   tokens = (const int*)d_in[0];
    const float* emb    = (const float*)d_in[1];
    const float* w_ih   = (const float*)d_in[2];
    const float* w_hh   = (const float*)d_in[3];
    const float* b_ih   = (const float*)d_in[4];
    const float* b_hh   = (const float*)d_in[5];
    float* out = (float*)d_out;

    cudaFuncSetAttribute(gru_kernel,
                         cudaFuncAttributeMaxDynamicSharedMemorySize, GRU_SMEM);

    gtab_kernel<<<dim3(G3 / 128, VB / 128), 256>>>(emb, w_ih, b_ih, tokens);
    gru_kernel<<<NCTA, 128, GRU_SMEM>>>(tokens, w_hh, b_hh, out);
}